// round 7
// baseline (speedup 1.0000x reference)
#include <cuda_runtime.h>

#define THR 1.2f

// [tb][pixel][half] 32-bit channel spike masks from layer 1 (4 MB)
__device__ unsigned g_mask[512 * 1024 * 2];
// per-block FC partial sums: 1024 blocks x 10 classes
__device__ float g_part[1024 * 10];

// ---------------------------------------------------------------------------
// Kernel 1: conv1 (3->64, 3x3, pad 1) + LIF threshold -> channel bitmasks
// Grid: 512 blocks (one per (t,b) image), 256 threads.
// 3 independent accumulator chains (one per cin) to break the FFMA RAW chain.
// ---------------------------------------------------------------------------
__global__ __launch_bounds__(256) void k1_conv1(const float* __restrict__ x,
                                                const float* __restrict__ w1,
                                                const float* __restrict__ b1) {
    __shared__ float xs[3 * 34 * 34];   // input with zero halo
    __shared__ float ws[64 * 27];
    __shared__ float bs[64];

    const int tb  = blockIdx.x;
    const int tid = threadIdx.x;

    for (int i = tid; i < 64 * 27; i += 256) ws[i] = w1[i];
    if (tid < 64) bs[tid] = b1[tid];

    const float* xin = x + tb * 3 * 1024;
    for (int i = tid; i < 3 * 34 * 34; i += 256) {
        int cin = i / 1156, rem = i - cin * 1156;
        int yy = rem / 34, xx = rem - yy * 34;
        int gy = yy - 1, gx = xx - 1;
        float v = 0.f;
        if (gy >= 0 && gy < 32 && gx >= 0 && gx < 32)
            v = xin[cin * 1024 + gy * 32 + gx];
        xs[i] = v;
    }
    __syncthreads();

    const int wid  = tid >> 5;
    const int lane = tid & 31;
    const int half = wid & 1;           // which 32-channel group this warp owns
    const int c    = half * 32 + lane;  // lane -> output channel

    float wr[27];
#pragma unroll
    for (int k = 0; k < 27; k++) wr[k] = ws[c * 27 + k];  // stride 27: conflict-free
    const float bias = bs[c];

#pragma unroll 2
    for (int p = (wid >> 1); p < 1024; p += 4) {
        const int y = p >> 5, xcol = p & 31;
        const float* xp = xs + y * 34 + xcol;
        float s0 = 0.f, s1 = 0.f, s2 = 0.f;
#pragma unroll
        for (int k = 0; k < 9; k++) {
            const int ky = k / 3, kx = k - ky * 3;
            s0 += wr[k]      * xp[ky * 34 + kx];
            s1 += wr[9 + k]  * xp[1156 + ky * 34 + kx];
            s2 += wr[18 + k] * xp[2312 + ky * 34 + kx];
        }
        unsigned bal = __ballot_sync(0xffffffffu, (s0 + s1 + s2 + bias) >= THR);
        if (lane == 0) g_mask[(tb * 1024 + p) * 2 + half] = bal;
    }
}

// 4 packed-f32x2 FMAs: acc_pair += w_pair * {s,s}  (s = 0.0 or 1.0)
#define FFMA4X2(a0, a1, a2, a3, w0, w1, w2, w3, s2)        \
    asm("fma.rn.f32x2 %0, %4, %8, %0;\n\t"                 \
        "fma.rn.f32x2 %1, %5, %8, %1;\n\t"                 \
        "fma.rn.f32x2 %2, %6, %8, %2;\n\t"                 \
        "fma.rn.f32x2 %3, %7, %8, %3;"                     \
        : "+l"(a0), "+l"(a1), "+l"(a2), "+l"(a3)           \
        : "l"(w0), "l"(w1), "l"(w2), "l"(w3), "l"(s2))

// ---------------------------------------------------------------------------
// Kernel 2: conv2 (64->64, binary input) + LIF + count over t + fused FC.
// Grid: (8 row-strips, 64 batch, 2 co-halves), 128 threads = 4 rows x 32 cols.
// Spike bit -> packed {1.0,1.0} multiplier (sign-extend trick), unpredicated
// FFMA2 so the fma pipe sees exactly one packed op per 2 MACs.
// ---------------------------------------------------------------------------
__global__ __launch_bounds__(128) void k2_conv2(const float* __restrict__ w2,
                                                const float* __restrict__ b2,
                                                const float* __restrict__ wfc) {
    __shared__ uint2 sm_mask[8][6][34];              // [t][strip row + halo][x + halo]
    __shared__ __align__(16) float sm_w[9 * 64 * 8]; // [pos][cin][co8]
    __shared__ float sm_b[8];
    __shared__ float sm_red[4 * 10];

    const int sy  = blockIdx.x;              // row strip (4 rows each)
    const int b   = blockIdx.y;
    const int zc  = blockIdx.z;              // 0/1 -> output channels [0,32) / [32,64)
    const int tid = threadIdx.x;
    const int ry  = tid >> 5;                // row within strip
    const int xc  = tid & 31;

    // Stage spike masks for this (b, strip) incl. halo, all 8 timesteps.
    for (int i = tid; i < 8 * 6 * 34; i += 128) {
        int t = i / 204, rem = i - t * 204;
        int r = rem / 34, xi = rem - r * 34;
        int gy = sy * 4 - 1 + r;
        int gx = xi - 1;
        uint2 v = make_uint2(0u, 0u);
        if (gy >= 0 && gy < 32 && gx >= 0 && gx < 32) {
            const uint2* gm = (const uint2*)g_mask;
            v = gm[(t * 64 + b) * 1024 + gy * 32 + gx];
        }
        sm_mask[t][r][xi] = v;
    }

    float outacc[10];
#pragma unroll
    for (int o = 0; o < 10; o++) outacc[o] = 0.f;

    const int gp = (sy * 4 + ry) * 32 + xc;  // global pixel index

    for (int chunk = 0; chunk < 4; chunk++) {
        const int coBase = zc * 32 + chunk * 8;
        __syncthreads();
        // sm_w[(pos*64+cin)*8 + co8] = w2[(coBase+co8)*576 + cin*9 + pos]
        for (int i = tid; i < 4608; i += 128) {
            int co8 = i / 576;               // coalesced over 'rest'
            int rest = i - co8 * 576;        // = cin*9 + pos
            int cin = rest / 9, pos = rest - cin * 9;
            sm_w[(pos * 64 + cin) * 8 + co8] = w2[(coBase + co8) * 576 + rest];
        }
        if (tid < 8) sm_b[tid] = b2[coBase + tid];
        __syncthreads();

        unsigned long long acc[8][4];        // [t][channel pair], packed f32x2
#pragma unroll
        for (int t = 0; t < 8; t++) {
#pragma unroll
            for (int q = 0; q < 4; q++) acc[t][q] = 0ull;
        }

#pragma unroll 1
        for (int dy = 0; dy < 3; dy++) {
#pragma unroll 1
            for (int dx = 0; dx < 3; dx++) {
                const int pos = dy * 3 + dx;
                unsigned mx[8], my[8];
#pragma unroll
                for (int t = 0; t < 8; t++) {
                    uint2 m = sm_mask[t][ry + dy][xc + dx];
                    mx[t] = m.x; my[t] = m.y;
                }
                const ulonglong2* wp = (const ulonglong2*)sm_w + pos * 64 * 2;

                // cins 0..31 (mx)
#pragma unroll 1
                for (int cg = 0; cg < 4; cg++) {
                    const int kb = 31 - cg * 8;
#pragma unroll
                    for (int u = 0; u < 8; u++) {
                        const int ksh = kb - u;          // shift to move bit to MSB
                        ulonglong2 w01 = wp[(cg * 8 + u) * 2];
                        ulonglong2 w23 = wp[(cg * 8 + u) * 2 + 1];
#pragma unroll
                        for (int t = 0; t < 8; t++) {
                            unsigned sb = ((unsigned)(((int)(mx[t] << ksh)) >> 31))
                                          & 0x3F800000u;
                            unsigned long long s2 =
                                ((unsigned long long)sb << 32) | sb;
                            FFMA4X2(acc[t][0], acc[t][1], acc[t][2], acc[t][3],
                                    w01.x, w01.y, w23.x, w23.y, s2);
                        }
                    }
                }
                // cins 32..63 (my)
#pragma unroll 1
                for (int cg = 0; cg < 4; cg++) {
                    const int kb = 31 - cg * 8;
#pragma unroll
                    for (int u = 0; u < 8; u++) {
                        const int ksh = kb - u;
                        ulonglong2 w01 = wp[(32 + cg * 8 + u) * 2];
                        ulonglong2 w23 = wp[(32 + cg * 8 + u) * 2 + 1];
#pragma unroll
                        for (int t = 0; t < 8; t++) {
                            unsigned sb = ((unsigned)(((int)(my[t] << ksh)) >> 31))
                                          & 0x3F800000u;
                            unsigned long long s2 =
                                ((unsigned long long)sb << 32) | sb;
                            FFMA4X2(acc[t][0], acc[t][1], acc[t][2], acc[t][3],
                                    w01.x, w01.y, w23.x, w23.y, s2);
                        }
                    }
                }
            }
        }

        // threshold -> spike count over t, fold into FC
#pragma unroll
        for (int jp = 0; jp < 4; jp++) {
            const float bias0 = sm_b[jp * 2];
            const float bias1 = sm_b[jp * 2 + 1];
            float cnt0 = 0.f, cnt1 = 0.f;
#pragma unroll
            for (int t = 0; t < 8; t++) {
                float lo, hi;
                asm("mov.b64 {%0,%1}, %2;" : "=f"(lo), "=f"(hi) : "l"(acc[t][jp]));
                cnt0 += ((lo + bias0) >= THR) ? 1.f : 0.f;
                cnt1 += ((hi + bias1) >= THR) ? 1.f : 0.f;
            }
            const int fi0 = (coBase + jp * 2) * 1024 + gp;
            const int fi1 = fi0 + 1024;
#pragma unroll
            for (int o = 0; o < 10; o++)
                outacc[o] += cnt0 * __ldg(&wfc[o * 65536 + fi0])
                           + cnt1 * __ldg(&wfc[o * 65536 + fi1]);
        }
    }

    // block reduction of the 10 partial class sums
    const int lane = tid & 31, wid = tid >> 5;
#pragma unroll
    for (int o = 0; o < 10; o++) {
        float v = outacc[o];
        v += __shfl_down_sync(0xffffffffu, v, 16);
        v += __shfl_down_sync(0xffffffffu, v, 8);
        v += __shfl_down_sync(0xffffffffu, v, 4);
        v += __shfl_down_sync(0xffffffffu, v, 2);
        v += __shfl_down_sync(0xffffffffu, v, 1);
        if (lane == 0) sm_red[wid * 10 + o] = v;
    }
    __syncthreads();
    if (tid < 10) {
        float s = sm_red[tid] + sm_red[10 + tid] + sm_red[20 + tid] + sm_red[30 + tid];
        const int blockLin = (b * 8 + sy) * 2 + zc;  // = b*16 + sy*2 + zc
        g_part[blockLin * 10 + tid] = s;
    }
}

// ---------------------------------------------------------------------------
// Kernel 3: deterministic final reduction: out[b][o] = 8*bfc[o] + sum(parts)
// ---------------------------------------------------------------------------
__global__ void k3_final(const float* __restrict__ bfc, float* __restrict__ out) {
    const int tid = threadIdx.x;
    if (tid < 640) {
        const int b = tid / 10, o = tid - b * 10;
        float s = 8.f * bfc[o];
#pragma unroll
        for (int k = 0; k < 16; k++) s += g_part[(b * 16 + k) * 10 + o];
        out[tid] = s;
    }
}

extern "C" void kernel_launch(void* const* d_in, const int* in_sizes, int n_in,
                              void* d_out, int out_size) {
    const float* x   = (const float*)d_in[0];  // [8,64,3,32,32]
    const float* w1  = (const float*)d_in[1];  // [64,3,3,3]
    const float* b1  = (const float*)d_in[2];  // [64]
    const float* w2  = (const float*)d_in[3];  // [64,64,3,3]
    const float* b2  = (const float*)d_in[4];  // [64]
    const float* wfc = (const float*)d_in[5];  // [10, 65536]
    const float* bfc = (const float*)d_in[6];  // [10]
    float* out = (float*)d_out;                // [64,10]

    k1_conv1<<<512, 256>>>(x, w1, b1);
    k2_conv2<<<dim3(8, 64, 2), 128>>>(w2, b2, wfc);
    k3_final<<<1, 640>>>(bfc, out);
}

// round 9
// speedup vs baseline: 2.4877x; 2.4877x over previous
#include <cuda_runtime.h>
#include <cuda_bf16.h>

#define THR 1.2f

// ---------------------------------------------------------------------------
// Device globals
// ---------------------------------------------------------------------------
__device__ unsigned g_mask[512 * 1024 * 2];          // [t*64+b][px] uint2 channel masks
__device__ float    g_part[512 * 10];                // per-block FC partials
__device__ __nv_bfloat16 g_wsp[2 * 9 * 64 * 64];     // [pass][pos][cin][co] split w2
__device__ float    g_wfcT[65536 * 12];              // [co*1024+px][12] transposed wfc

__device__ __forceinline__ unsigned smem_u32(const void* p) {
    unsigned a;
    asm("{ .reg .u64 t; cvta.to.shared.u64 t, %1; cvt.u32.u64 %0, t; }"
        : "=r"(a) : "l"(p));
    return a;
}

// ldmatrix: four 8x8 b16 tiles (16x16). Lane l addr: row = l&15, +16B col for l>=16.
#define LDMX4(r, addr) \
    asm volatile("ldmatrix.sync.aligned.m8n8.x4.shared.b16 {%0,%1,%2,%3}, [%4];" \
        : "=r"((r)[0]), "=r"((r)[1]), "=r"((r)[2]), "=r"((r)[3]) : "r"(addr))
#define LDMX4T(r, addr) \
    asm volatile("ldmatrix.sync.aligned.m8n8.x4.trans.shared.b16 {%0,%1,%2,%3}, [%4];" \
        : "=r"((r)[0]), "=r"((r)[1]), "=r"((r)[2]), "=r"((r)[3]) : "r"(addr))

#define MMA16816(c, a, bb0, bb1) \
    asm volatile("mma.sync.aligned.m16n8k16.row.col.f32.bf16.bf16.f32 " \
        "{%0,%1,%2,%3}, {%4,%5,%6,%7}, {%8,%9}, {%0,%1,%2,%3};" \
        : "+f"((c)[0]), "+f"((c)[1]), "+f"((c)[2]), "+f"((c)[3]) \
        : "r"((a)[0]), "r"((a)[1]), "r"((a)[2]), "r"((a)[3]), "r"(bb0), "r"(bb1))

// ---------------------------------------------------------------------------
// Kernel 1: conv1 (3->64) + LIF -> channel bitmasks (unchanged)
// ---------------------------------------------------------------------------
__global__ __launch_bounds__(256) void k1_conv1(const float* __restrict__ x,
                                                const float* __restrict__ w1,
                                                const float* __restrict__ b1) {
    __shared__ float xs[3 * 34 * 34];
    __shared__ float ws[64 * 27];
    __shared__ float bs[64];

    const int tb  = blockIdx.x;
    const int tid = threadIdx.x;

    for (int i = tid; i < 64 * 27; i += 256) ws[i] = w1[i];
    if (tid < 64) bs[tid] = b1[tid];

    const float* xin = x + tb * 3 * 1024;
    for (int i = tid; i < 3 * 34 * 34; i += 256) {
        int cin = i / 1156, rem = i - cin * 1156;
        int yy = rem / 34, xx = rem - yy * 34;
        int gy = yy - 1, gx = xx - 1;
        float v = 0.f;
        if (gy >= 0 && gy < 32 && gx >= 0 && gx < 32)
            v = xin[cin * 1024 + gy * 32 + gx];
        xs[i] = v;
    }
    __syncthreads();

    const int wid  = tid >> 5;
    const int lane = tid & 31;
    const int half = wid & 1;
    const int c    = half * 32 + lane;

    float wr[27];
#pragma unroll
    for (int k = 0; k < 27; k++) wr[k] = ws[c * 27 + k];
    const float bias = bs[c];

#pragma unroll 2
    for (int p = (wid >> 1); p < 1024; p += 4) {
        const int y = p >> 5, xcol = p & 31;
        const float* xp = xs + y * 34 + xcol;
        float s0 = 0.f, s1 = 0.f, s2 = 0.f;
#pragma unroll
        for (int k = 0; k < 9; k++) {
            const int ky = k / 3, kx = k - ky * 3;
            s0 += wr[k]      * xp[ky * 34 + kx];
            s1 += wr[9 + k]  * xp[1156 + ky * 34 + kx];
            s2 += wr[18 + k] * xp[2312 + ky * 34 + kx];
        }
        unsigned bal = __ballot_sync(0xffffffffu, (s0 + s1 + s2 + bias) >= THR);
        if (lane == 0) g_mask[(tb * 1024 + p) * 2 + half] = bal;
    }
}

// ---------------------------------------------------------------------------
// Kernel 2a: split w2 -> bf16 hi+lo, layout [pass][pos][cin][co] (k-major rows)
// ---------------------------------------------------------------------------
__global__ void k2a_split(const float* __restrict__ w2) {
    int i = blockIdx.x * 256 + threadIdx.x;
    if (i >= 36864) return;
    int co = i / 576, rest = i - co * 576;
    int cin = rest / 9, pos = rest - cin * 9;   // pos = ky*3+kx
    float w = w2[i];
    __nv_bfloat16 hi = __float2bfloat16(w);
    __nv_bfloat16 lo = __float2bfloat16(w - __bfloat162float(hi));
    int idx = pos * 4096 + cin * 64 + co;
    g_wsp[idx] = hi;
    g_wsp[36864 + idx] = lo;
}

// ---------------------------------------------------------------------------
// Kernel 2b: transpose wfc -> [co*1024+px][12]
// ---------------------------------------------------------------------------
__global__ void k2b_transpose(const float* __restrict__ wfc) {
    int i = blockIdx.x * 256 + threadIdx.x;   // 0..65535
    float v[10];
#pragma unroll
    for (int o = 0; o < 10; o++) v[o] = wfc[o * 65536 + i];
    float4* dst = (float4*)(g_wfcT + i * 12);
    dst[0] = make_float4(v[0], v[1], v[2], v[3]);
    dst[1] = make_float4(v[4], v[5], v[6], v[7]);
    dst[2] = make_float4(v[8], v[9], 0.f, 0.f);
}

// ---------------------------------------------------------------------------
// Kernel 2: conv2 via mma.sync bf16 (hi/lo split) + LIF + count over t + FC
// Grid: (8 strips, 64 b), 256 threads = 8 warps; warp = (row ry, x-half).
// SMEM: thr2[64] @0 (256B) | red @256 (320B) | LUT @1024 (4KB)
//       weights @5120: 18 tables x 64 rows x 128B, chunk-swizzled (147456B)
//       planes  @152576: 2 t x 204 rows x 128B, chunk-swizzled (52224B)
// ---------------------------------------------------------------------------
#define OFF_RED   256
#define OFF_LUT   1024
#define OFF_B     5120
#define OFF_PLANE 152576
#define SMEM_K2   204800

__global__ __launch_bounds__(256, 1) void k2_mma(const float* __restrict__ b2) {
    extern __shared__ __align__(128) char sm[];
    const unsigned smb = smem_u32(sm);

    const int sy  = blockIdx.x;
    const int b   = blockIdx.y;
    const int tid = threadIdx.x;
    const int wid = tid >> 5;
    const int lane = tid & 31;
    const int ry = wid >> 1;          // image row within strip (0..3)
    const int xhalf = wid & 1;        // x 0..15 / 16..31

    // LUT: byte -> 8 bf16 (0/1), 16B per entry
    if (tid < 256) {
        int v = tid;
        unsigned w[4];
#pragma unroll
        for (int i = 0; i < 4; i++) {
            unsigned lo = ((v >> (2 * i)) & 1)     ? 0x3F80u : 0u;
            unsigned hi = ((v >> (2 * i + 1)) & 1) ? 0x3F800000u : 0u;
            w[i] = lo | hi;
        }
        *(uint4*)(sm + OFF_LUT + v * 16) = make_uint4(w[0], w[1], w[2], w[3]);
    }
    if (tid < 64) ((float*)sm)[tid] = THR - b2[tid];

    // weights -> SMEM with chunk swizzle j ^= (row&7)
    {
        const char* src = (const char*)g_wsp;
        for (int i = tid; i < 9216; i += 256) {
            int off = i * 16;
            int inner = off & 8191;
            int r = inner >> 7, j = (inner >> 4) & 7;
            uint4 v = *(const uint4*)(src + off);
            *(uint4*)(sm + OFF_B + (off & ~8191) + (r << 7) + ((j ^ (r & 7)) << 4)) = v;
        }
    }
    __syncthreads();

    float thr2v[16];
#pragma unroll
    for (int nf = 0; nf < 8; nf++) {
        thr2v[nf * 2]     = ((const float*)sm)[nf * 8 + (lane & 3) * 2];
        thr2v[nf * 2 + 1] = ((const float*)sm)[nf * 8 + (lane & 3) * 2 + 1];
    }

    float cnt[8][4];
#pragma unroll
    for (int nf = 0; nf < 8; nf++)
#pragma unroll
        for (int q = 0; q < 4; q++) cnt[nf][q] = 0.f;

    const uint2* gm = (const uint2*)g_mask;

    for (int tp = 0; tp < 4; tp++) {
        // --- expand spike masks for t=2tp, 2tp+1 into bf16 planes (204 rows each)
        for (int i = tid; i < 408; i += 256) {
            int tl = (i >= 204) ? 1 : 0;
            int r = i - tl * 204;
            int iy = r / 34, ixp = r - iy * 34;
            int y = sy * 4 - 1 + iy;
            int ix = ixp - 1;
            uint2 m = make_uint2(0u, 0u);
            if ((unsigned)y < 32u && (unsigned)ix < 32u)
                m = gm[((tp * 2 + tl) * 64 + b) * 1024 + y * 32 + ix];
            char* pb = sm + OFF_PLANE + tl * 26112 + r * 128;
            const int rs = r & 7;
#pragma unroll
            for (int k = 0; k < 4; k++) {
                unsigned byte = (m.x >> (8 * k)) & 0xFFu;
                uint4 v = *(const uint4*)(sm + OFF_LUT + byte * 16);
                *(uint4*)(pb + ((k ^ rs) << 4)) = v;
            }
#pragma unroll
            for (int k = 4; k < 8; k++) {
                unsigned byte = (m.y >> (8 * (k - 4))) & 0xFFu;
                uint4 v = *(const uint4*)(sm + OFF_LUT + byte * 16);
                *(uint4*)(pb + ((k ^ rs) << 4)) = v;
            }
        }
        __syncthreads();

        float c[2][8][4];
#pragma unroll
        for (int tl = 0; tl < 2; tl++)
#pragma unroll
            for (int nf = 0; nf < 8; nf++)
#pragma unroll
                for (int q = 0; q < 4; q++) c[tl][nf][q] = 0.f;

        const unsigned p0 = smb + OFF_PLANE;
        const unsigned p1 = p0 + 26112;

#pragma unroll 1
        for (int pos = 0; pos < 9; pos++) {
            const int dy = pos / 3, dx = pos - dy * 3;
            const int prb = (ry + dy) * 34 + xhalf * 16 + dx + (lane & 15);
            const unsigned wtb = smb + OFF_B + pos * 8192;
#pragma unroll 1
            for (int kt = 0; kt < 4; kt++) {
                const unsigned aoff =
                    prb * 128 + (((unsigned)(kt * 2 + (lane >> 4)) ^ (prb & 7)) << 4);
                unsigned a0[4], a1[4];
                LDMX4(a0, p0 + aoff);
                LDMX4(a1, p1 + aoff);
                const int brow = kt * 16 + (lane & 15);
                const unsigned bjb = (unsigned)(lane >> 4);
                const unsigned bbase = brow * 128;
#pragma unroll
                for (int pass = 0; pass < 2; pass++) {
                    const unsigned wb = wtb + pass * 73728 + bbase;
#pragma unroll
                    for (int nt = 0; nt < 4; nt++) {
                        unsigned bb[4];
                        LDMX4T(bb, wb + (((nt * 2 + bjb) ^ (brow & 7)) << 4));
                        MMA16816(c[0][nt * 2],     a0, bb[0], bb[1]);
                        MMA16816(c[0][nt * 2 + 1], a0, bb[2], bb[3]);
                        MMA16816(c[1][nt * 2],     a1, bb[0], bb[1]);
                        MMA16816(c[1][nt * 2 + 1], a1, bb[2], bb[3]);
                    }
                }
            }
        }

        // threshold both timesteps -> spike counts
#pragma unroll
        for (int tl = 0; tl < 2; tl++)
#pragma unroll
            for (int nf = 0; nf < 8; nf++)
#pragma unroll
                for (int q = 0; q < 4; q++)
                    cnt[nf][q] += (c[tl][nf][q] >= thr2v[nf * 2 + (q & 1)]) ? 1.f : 0.f;

        __syncthreads();   // readers done before next tp overwrites planes
    }

    // --- fused FC fold: element (nf,q) -> (px, co)
    float oa[10];
#pragma unroll
    for (int o = 0; o < 10; o++) oa[o] = 0.f;
    const int gpbase = (sy * 4 + ry) * 32 + xhalf * 16;
#pragma unroll
    for (int q = 0; q < 4; q++) {
        const int gp = gpbase + (lane >> 2) + ((q >> 1) << 3);
#pragma unroll
        for (int nf = 0; nf < 8; nf++) {
            const int co = nf * 8 + (lane & 3) * 2 + (q & 1);
            const float4* p = (const float4*)(g_wfcT + (co * 1024 + gp) * 12);
            float4 f0 = p[0], f1 = p[1], f2 = p[2];
            const float cc = cnt[nf][q];
            oa[0] += cc * f0.x; oa[1] += cc * f0.y; oa[2] += cc * f0.z; oa[3] += cc * f0.w;
            oa[4] += cc * f1.x; oa[5] += cc * f1.y; oa[6] += cc * f1.z; oa[7] += cc * f1.w;
            oa[8] += cc * f2.x; oa[9] += cc * f2.y;
        }
    }

    float* red = (float*)(sm + OFF_RED);
#pragma unroll
    for (int o = 0; o < 10; o++) {
        float v = oa[o];
        v += __shfl_down_sync(0xffffffffu, v, 16);
        v += __shfl_down_sync(0xffffffffu, v, 8);
        v += __shfl_down_sync(0xffffffffu, v, 4);
        v += __shfl_down_sync(0xffffffffu, v, 2);
        v += __shfl_down_sync(0xffffffffu, v, 1);
        if (lane == 0) red[wid * 10 + o] = v;
    }
    __syncthreads();
    if (tid < 10) {
        float s = 0.f;
#pragma unroll
        for (int w = 0; w < 8; w++) s += red[w * 10 + tid];
        g_part[(b * 8 + sy) * 10 + tid] = s;
    }
}

// ---------------------------------------------------------------------------
// Kernel 3: final reduction
// ---------------------------------------------------------------------------
__global__ void k3_final(const float* __restrict__ bfc, float* __restrict__ out) {
    const int tid = threadIdx.x;
    if (tid < 640) {
        const int b = tid / 10, o = tid - b * 10;
        float s = 8.f * bfc[o];
#pragma unroll
        for (int k = 0; k < 8; k++) s += g_part[(b * 8 + k) * 10 + o];
        out[tid] = s;
    }
}

extern "C" void kernel_launch(void* const* d_in, const int* in_sizes, int n_in,
                              void* d_out, int out_size) {
    const float* x   = (const float*)d_in[0];  // [8,64,3,32,32]
    const float* w1  = (const float*)d_in[1];  // [64,3,3,3]
    const float* b1  = (const float*)d_in[2];  // [64]
    const float* w2  = (const float*)d_in[3];  // [64,64,3,3]
    const float* b2  = (const float*)d_in[4];  // [64]
    const float* wfc = (const float*)d_in[5];  // [10, 65536]
    const float* bfc = (const float*)d_in[6];  // [10]
    float* out = (float*)d_out;                // [64,10]

    cudaFuncSetAttribute(k2_mma, cudaFuncAttributeMaxDynamicSharedMemorySize,
                         SMEM_K2);

    k1_conv1<<<512, 256>>>(x, w1, b1);
    k2a_split<<<144, 256>>>(w2);
    k2b_transpose<<<256, 256>>>(wfc);
    k2_mma<<<dim3(8, 64), 256, SMEM_K2>>>(b2);
    k3_final<<<1, 640>>>(bfc, out);
}

// round 10
// speedup vs baseline: 3.1228x; 1.2553x over previous
#include <cuda_runtime.h>
#include <cuda_bf16.h>

#define THR 1.2f

// ---------------------------------------------------------------------------
// Device globals
// ---------------------------------------------------------------------------
__device__ unsigned g_mask[512 * 1024 * 2];          // [t*64+b][px] uint2 channel masks
__device__ float    g_part[256 * 10];                // per-block FC partials
__device__ __nv_bfloat16 g_wsp[2 * 9 * 64 * 64];     // [pass][pos][cin][co] split w2
__device__ float    g_wfcT[65536 * 12];              // [co*1024+px][12] transposed wfc

__device__ __forceinline__ unsigned smem_u32(const void* p) {
    unsigned a;
    asm("{ .reg .u64 t; cvta.to.shared.u64 t, %1; cvt.u32.u64 %0, t; }"
        : "=r"(a) : "l"(p));
    return a;
}

#define LDMX4(r, addr) \
    asm volatile("ldmatrix.sync.aligned.m8n8.x4.shared.b16 {%0,%1,%2,%3}, [%4];" \
        : "=r"((r)[0]), "=r"((r)[1]), "=r"((r)[2]), "=r"((r)[3]) : "r"(addr))
#define LDMX4T(r, addr) \
    asm volatile("ldmatrix.sync.aligned.m8n8.x4.trans.shared.b16 {%0,%1,%2,%3}, [%4];" \
        : "=r"((r)[0]), "=r"((r)[1]), "=r"((r)[2]), "=r"((r)[3]) : "r"(addr))
#define MMA16816(c, a, bb0, bb1) \
    asm volatile("mma.sync.aligned.m16n8k16.row.col.f32.bf16.bf16.f32 " \
        "{%0,%1,%2,%3}, {%4,%5,%6,%7}, {%8,%9}, {%0,%1,%2,%3};" \
        : "+f"((c)[0]), "+f"((c)[1]), "+f"((c)[2]), "+f"((c)[3]) \
        : "r"((a)[0]), "r"((a)[1]), "r"((a)[2]), "r"((a)[3]), "r"(bb0), "r"(bb1))

// packed f32x2 helpers for k1
#define PACK2(d, x)   asm("mov.b64 %0, {%1,%1};" : "=l"(d) : "f"(x))
#define PACKAB(d, a, b) asm("mov.b64 %0, {%1,%2};" : "=l"(d) : "f"(a), "f"(b))
#define FMA2(acc, w, x2) \
    asm("fma.rn.f32x2 %0, %1, %2, %0;" : "+l"(acc) : "l"(w), "l"(x2))
#define UNPACK2(lo, hi, v) \
    asm("mov.b64 {%0,%1}, %2;" : "=f"(lo), "=f"(hi) : "l"(v))

// ---------------------------------------------------------------------------
// Kernel 1: conv1 (3->64) + LIF -> channel bitmasks.
// Block = one (t,b) image, 256 threads = 8 warps. Lane = channel PAIR
// (c, c+32) via packed f32x2; thread handles 8 consecutive pixels.
// ---------------------------------------------------------------------------
__global__ __launch_bounds__(256) void k1_conv1(const float* __restrict__ x,
                                                const float* __restrict__ w1,
                                                const float* __restrict__ b1) {
    __shared__ float xs[3 * 34 * 36];   // rows padded to 36 for vec4 loads
    __shared__ float ws[64 * 27];
    __shared__ float bs[64];

    const int tb  = blockIdx.x;
    const int tid = threadIdx.x;

    for (int i = tid; i < 64 * 27; i += 256) ws[i] = w1[i];
    if (tid < 64) bs[tid] = b1[tid];

    const float* xin = x + tb * 3 * 1024;
    for (int i = tid; i < 3 * 34 * 34; i += 256) {
        int cin = i / 1156, rem = i - cin * 1156;
        int yy = rem / 34, xx = rem - yy * 34;
        int gy = yy - 1, gx = xx - 1;
        float v = 0.f;
        if (gy >= 0 && gy < 32 && gx >= 0 && gx < 32)
            v = xin[cin * 1024 + gy * 32 + gx];
        xs[cin * 1224 + yy * 36 + xx] = v;
    }
    __syncthreads();

    const int wid  = tid >> 5;
    const int lane = tid & 31;          // channel pair: (lane, lane+32)

    unsigned long long wp[27];
#pragma unroll
    for (int k = 0; k < 27; k++)
        PACKAB(wp[k], ws[lane * 27 + k], ws[(lane + 32) * 27 + k]);
    unsigned long long bias2;
    PACKAB(bias2, bs[lane], bs[lane + 32]);

    for (int seg = wid; seg < 128; seg += 8) {
        const int y   = seg >> 2;        // output row 0..31
        const int xc0 = (seg & 3) * 8;   // output col base

        unsigned long long acc2[8];
#pragma unroll
        for (int px = 0; px < 8; px++) acc2[px] = bias2;

#pragma unroll
        for (int cin = 0; cin < 3; cin++) {
            const float* base = xs + cin * 1224 + xc0;
#pragma unroll
            for (int dr = 0; dr < 3; dr++) {
                // xs row index = (y + dr); window cols xc0..xc0+9 (12 loaded)
                const float4* rp = (const float4*)(base + (y + dr) * 36);
                float4 f0 = rp[0], f1 = rp[1], f2 = rp[2];
                unsigned long long x2[12];
                PACK2(x2[0], f0.x); PACK2(x2[1], f0.y); PACK2(x2[2], f0.z); PACK2(x2[3], f0.w);
                PACK2(x2[4], f1.x); PACK2(x2[5], f1.y); PACK2(x2[6], f1.z); PACK2(x2[7], f1.w);
                PACK2(x2[8], f2.x); PACK2(x2[9], f2.y);
                x2[10] = 0; x2[11] = 0;  // unused
                const int wb = cin * 9 + dr * 3;
#pragma unroll
                for (int px = 0; px < 8; px++) {
                    FMA2(acc2[px], wp[wb],     x2[px]);
                    FMA2(acc2[px], wp[wb + 1], x2[px + 1]);
                    FMA2(acc2[px], wp[wb + 2], x2[px + 2]);
                }
            }
        }

#pragma unroll
        for (int px = 0; px < 8; px++) {
            float lo, hi;
            UNPACK2(lo, hi, acc2[px]);
            unsigned mlo = __ballot_sync(0xffffffffu, lo >= THR);
            unsigned mhi = __ballot_sync(0xffffffffu, hi >= THR);
            if (lane == 0)
                ((uint2*)g_mask)[tb * 1024 + seg * 8 + px] = make_uint2(mlo, mhi);
        }
    }
}

// ---------------------------------------------------------------------------
// Kernel 2a: split w2 -> bf16 hi+lo, layout [pass][pos][cin][co]
// ---------------------------------------------------------------------------
__global__ void k2a_split(const float* __restrict__ w2) {
    int i = blockIdx.x * 256 + threadIdx.x;
    if (i >= 36864) return;
    int co = i / 576, rest = i - co * 576;
    int cin = rest / 9, pos = rest - cin * 9;
    float w = w2[i];
    __nv_bfloat16 hi = __float2bfloat16(w);
    __nv_bfloat16 lo = __float2bfloat16(w - __bfloat162float(hi));
    int idx = pos * 4096 + cin * 64 + co;
    g_wsp[idx] = hi;
    g_wsp[36864 + idx] = lo;
}

// ---------------------------------------------------------------------------
// Kernel 2b: transpose wfc -> [co*1024+px][12]
// ---------------------------------------------------------------------------
__global__ void k2b_transpose(const float* __restrict__ wfc) {
    int i = blockIdx.x * 256 + threadIdx.x;   // 0..65535
    float v[10];
#pragma unroll
    for (int o = 0; o < 10; o++) v[o] = wfc[o * 65536 + i];
    float4* dst = (float4*)(g_wfcT + i * 12);
    dst[0] = make_float4(v[0], v[1], v[2], v[3]);
    dst[1] = make_float4(v[4], v[5], v[6], v[7]);
    dst[2] = make_float4(v[8], v[9], 0.f, 0.f);
}

// ---------------------------------------------------------------------------
// Kernel 2: conv2 via mma.sync bf16 (hi/lo) + LIF + count over t + FC.
// Grid: (4 strips of 8 rows, 64 b), 512 threads = 16 warps (4/SMSP).
// One timestep per phase; plane = 340 rows x 128B.
// SMEM: thr2 @0 (256B) | red @256 (640B) | LUT @1024 (4KB)
//       weights @5120 (147456B) | plane @152576 (43520B) -> 196096B
// ---------------------------------------------------------------------------
#define OFF_RED   256
#define OFF_LUT   1024
#define OFF_B     5120
#define OFF_PLANE 152576
#define SMEM_K2   196096

__global__ __launch_bounds__(512, 1) void k2_mma(const float* __restrict__ b2) {
    extern __shared__ __align__(128) char sm[];
    const unsigned smb = smem_u32(sm);

    const int sy  = blockIdx.x;       // 8-row strip (0..3)
    const int b   = blockIdx.y;
    const int tid = threadIdx.x;
    const int wid = tid >> 5;
    const int lane = tid & 31;
    const int ry = wid >> 1;          // image row within strip (0..7)
    const int xhalf = wid & 1;

    // LUT: byte -> 8 bf16 (0/1)
    if (tid < 256) {
        int v = tid;
        unsigned w[4];
#pragma unroll
        for (int i = 0; i < 4; i++) {
            unsigned lo = ((v >> (2 * i)) & 1)     ? 0x3F80u : 0u;
            unsigned hi = ((v >> (2 * i + 1)) & 1) ? 0x3F800000u : 0u;
            w[i] = lo | hi;
        }
        *(uint4*)(sm + OFF_LUT + v * 16) = make_uint4(w[0], w[1], w[2], w[3]);
    }
    if (tid < 64) ((float*)sm)[tid] = THR - b2[tid];

    // weights -> SMEM with chunk swizzle j ^= (row&7)
    {
        const char* src = (const char*)g_wsp;
        for (int i = tid; i < 9216; i += 512) {
            int off = i * 16;
            int inner = off & 8191;
            int r = inner >> 7, j = (inner >> 4) & 7;
            uint4 v = *(const uint4*)(src + off);
            *(uint4*)(sm + OFF_B + (off & ~8191) + (r << 7) + ((j ^ (r & 7)) << 4)) = v;
        }
    }
    __syncthreads();

    float thr2v[16];
#pragma unroll
    for (int nf = 0; nf < 8; nf++) {
        thr2v[nf * 2]     = ((const float*)sm)[nf * 8 + (lane & 3) * 2];
        thr2v[nf * 2 + 1] = ((const float*)sm)[nf * 8 + (lane & 3) * 2 + 1];
    }

    float cnt[8][4];
#pragma unroll
    for (int nf = 0; nf < 8; nf++)
#pragma unroll
        for (int q = 0; q < 4; q++) cnt[nf][q] = 0.f;

    const uint2* gm = (const uint2*)g_mask;
    const unsigned p0 = smb + OFF_PLANE;

    for (int t = 0; t < 8; t++) {
        // --- expand spike masks for this t: 340 rows (10 image rows + x halo)
        if (tid < 340) {
            int r = tid;
            int iy = r / 34, ixp = r - iy * 34;
            int y = sy * 8 - 1 + iy;
            int ix = ixp - 1;
            uint2 m = make_uint2(0u, 0u);
            if ((unsigned)y < 32u && (unsigned)ix < 32u)
                m = gm[(t * 64 + b) * 1024 + y * 32 + ix];
            char* pb = sm + OFF_PLANE + r * 128;
            const int rs = r & 7;
#pragma unroll
            for (int k = 0; k < 4; k++) {
                unsigned byte = (m.x >> (8 * k)) & 0xFFu;
                uint4 v = *(const uint4*)(sm + OFF_LUT + byte * 16);
                *(uint4*)(pb + ((k ^ rs) << 4)) = v;
            }
#pragma unroll
            for (int k = 4; k < 8; k++) {
                unsigned byte = (m.y >> (8 * (k - 4))) & 0xFFu;
                uint4 v = *(const uint4*)(sm + OFF_LUT + byte * 16);
                *(uint4*)(pb + ((k ^ rs) << 4)) = v;
            }
        }
        __syncthreads();

        float c[8][4];
#pragma unroll
        for (int nf = 0; nf < 8; nf++)
#pragma unroll
            for (int q = 0; q < 4; q++) c[nf][q] = 0.f;

#pragma unroll 1
        for (int pos = 0; pos < 9; pos++) {
            const int dy = pos / 3, dx = pos - dy * 3;
            const int prb = (ry + dy) * 34 + xhalf * 16 + dx + (lane & 15);
            const unsigned wtb = smb + OFF_B + pos * 8192;
#pragma unroll 1
            for (int kt = 0; kt < 4; kt++) {
                const unsigned aoff =
                    prb * 128 + (((unsigned)(kt * 2 + (lane >> 4)) ^ (prb & 7)) << 4);
                unsigned a0[4];
                LDMX4(a0, p0 + aoff);
                const int brow = kt * 16 + (lane & 15);
                const unsigned bjb = (unsigned)(lane >> 4);
                const unsigned bbase = brow * 128;
#pragma unroll
                for (int pass = 0; pass < 2; pass++) {
                    const unsigned wb = wtb + pass * 73728 + bbase;
#pragma unroll
                    for (int nt = 0; nt < 4; nt++) {
                        unsigned bb[4];
                        LDMX4T(bb, wb + (((nt * 2 + bjb) ^ (brow & 7)) << 4));
                        MMA16816(c[nt * 2],     a0, bb[0], bb[1]);
                        MMA16816(c[nt * 2 + 1], a0, bb[2], bb[3]);
                    }
                }
            }
        }

        // threshold -> spike counts
#pragma unroll
        for (int nf = 0; nf < 8; nf++)
#pragma unroll
            for (int q = 0; q < 4; q++)
                cnt[nf][q] += (c[nf][q] >= thr2v[nf * 2 + (q & 1)]) ? 1.f : 0.f;

        __syncthreads();   // MMA reads done before next t overwrites plane
    }

    // --- fused FC fold
    float oa[10];
#pragma unroll
    for (int o = 0; o < 10; o++) oa[o] = 0.f;
    const int gpbase = (sy * 8 + ry) * 32 + xhalf * 16;
#pragma unroll
    for (int q = 0; q < 4; q++) {
        const int gp = gpbase + (lane >> 2) + ((q >> 1) << 3);
#pragma unroll
        for (int nf = 0; nf < 8; nf++) {
            const int co = nf * 8 + (lane & 3) * 2 + (q & 1);
            const float4* p = (const float4*)(g_wfcT + (co * 1024 + gp) * 12);
            float4 f0 = p[0], f1 = p[1], f2 = p[2];
            const float cc = cnt[nf][q];
            oa[0] += cc * f0.x; oa[1] += cc * f0.y; oa[2] += cc * f0.z; oa[3] += cc * f0.w;
            oa[4] += cc * f1.x; oa[5] += cc * f1.y; oa[6] += cc * f1.z; oa[7] += cc * f1.w;
            oa[8] += cc * f2.x; oa[9] += cc * f2.y;
        }
    }

    float* red = (float*)(sm + OFF_RED);
#pragma unroll
    for (int o = 0; o < 10; o++) {
        float v = oa[o];
        v += __shfl_down_sync(0xffffffffu, v, 16);
        v += __shfl_down_sync(0xffffffffu, v, 8);
        v += __shfl_down_sync(0xffffffffu, v, 4);
        v += __shfl_down_sync(0xffffffffu, v, 2);
        v += __shfl_down_sync(0xffffffffu, v, 1);
        if (lane == 0) red[wid * 10 + o] = v;
    }
    __syncthreads();
    if (tid < 10) {
        float s = 0.f;
#pragma unroll
        for (int w = 0; w < 16; w++) s += red[w * 10 + tid];
        g_part[(b * 4 + sy) * 10 + tid] = s;
    }
}

// ---------------------------------------------------------------------------
// Kernel 3: final reduction
// ---------------------------------------------------------------------------
__global__ void k3_final(const float* __restrict__ bfc, float* __restrict__ out) {
    const int tid = threadIdx.x;
    if (tid < 640) {
        const int b = tid / 10, o = tid - b * 10;
        float s = 8.f * bfc[o];
#pragma unroll
        for (int k = 0; k < 4; k++) s += g_part[(b * 4 + k) * 10 + o];
        out[tid] = s;
    }
}

extern "C" void kernel_launch(void* const* d_in, const int* in_sizes, int n_in,
                              void* d_out, int out_size) {
    const float* x   = (const float*)d_in[0];  // [8,64,3,32,32]
    const float* w1  = (const float*)d_in[1];  // [64,3,3,3]
    const float* b1  = (const float*)d_in[2];  // [64]
    const float* w2  = (const float*)d_in[3];  // [64,64,3,3]
    const float* b2  = (const float*)d_in[4];  // [64]
    const float* wfc = (const float*)d_in[5];  // [10, 65536]
    const float* bfc = (const float*)d_in[6];  // [10]
    float* out = (float*)d_out;                // [64,10]

    cudaFuncSetAttribute(k2_mma, cudaFuncAttributeMaxDynamicSharedMemorySize,
                         SMEM_K2);

    k1_conv1<<<512, 256>>>(x, w1, b1);
    k2a_split<<<144, 256>>>(w2);
    k2b_transpose<<<256, 256>>>(wfc);
    k2_mma<<<dim3(4, 64), 512, SMEM_K2>>>(b2);
    k3_final<<<1, 640>>>(bfc, out);
}

// round 11
// speedup vs baseline: 3.2542x; 1.0421x over previous
#include <cuda_runtime.h>
#include <cuda_bf16.h>

#define THR 1.2f

// ---------------------------------------------------------------------------
// Device globals
// ---------------------------------------------------------------------------
__device__ unsigned g_mask[512 * 1024 * 2];          // [t*64+b][px] uint2 channel masks
__device__ float    g_part[256 * 10];                // per-block FC partials
__device__ __nv_bfloat16 g_wsp[2 * 9 * 64 * 64];     // [pass][pos][cin][co] split w2
__device__ float    g_wfcT[65536 * 12];              // [co*1024+px][12] transposed wfc

__device__ __forceinline__ unsigned smem_u32(const void* p) {
    unsigned a;
    asm("{ .reg .u64 t; cvta.to.shared.u64 t, %1; cvt.u32.u64 %0, t; }"
        : "=r"(a) : "l"(p));
    return a;
}

#define LDMX4(r, addr) \
    asm volatile("ldmatrix.sync.aligned.m8n8.x4.shared.b16 {%0,%1,%2,%3}, [%4];" \
        : "=r"((r)[0]), "=r"((r)[1]), "=r"((r)[2]), "=r"((r)[3]) : "r"(addr))
#define LDMX4T(r, addr) \
    asm volatile("ldmatrix.sync.aligned.m8n8.x4.trans.shared.b16 {%0,%1,%2,%3}, [%4];" \
        : "=r"((r)[0]), "=r"((r)[1]), "=r"((r)[2]), "=r"((r)[3]) : "r"(addr))
#define MMA16816(c, a, bb0, bb1) \
    asm volatile("mma.sync.aligned.m16n8k16.row.col.f32.bf16.bf16.f32 " \
        "{%0,%1,%2,%3}, {%4,%5,%6,%7}, {%8,%9}, {%0,%1,%2,%3};" \
        : "+f"((c)[0]), "+f"((c)[1]), "+f"((c)[2]), "+f"((c)[3]) \
        : "r"((a)[0]), "r"((a)[1]), "r"((a)[2]), "r"((a)[3]), "r"(bb0), "r"(bb1))

// packed f32x2 helpers for k1
#define PACK2(d, x)   asm("mov.b64 %0, {%1,%1};" : "=l"(d) : "f"(x))
#define PACKAB(d, a, b) asm("mov.b64 %0, {%1,%2};" : "=l"(d) : "f"(a), "f"(b))
#define FMA2(acc, w, x2) \
    asm("fma.rn.f32x2 %0, %1, %2, %0;" : "+l"(acc) : "l"(w), "l"(x2))
#define UNPACK2(lo, hi, v) \
    asm("mov.b64 {%0,%1}, %2;" : "=f"(lo), "=f"(hi) : "l"(v))

// ---------------------------------------------------------------------------
// Kernel 1: conv1 (3->64) + LIF -> channel bitmasks (unchanged from R10)
// ---------------------------------------------------------------------------
__global__ __launch_bounds__(256) void k1_conv1(const float* __restrict__ x,
                                                const float* __restrict__ w1,
                                                const float* __restrict__ b1) {
    __shared__ float xs[3 * 34 * 36];   // rows padded to 36 for vec4 loads
    __shared__ float ws[64 * 27];
    __shared__ float bs[64];

    const int tb  = blockIdx.x;
    const int tid = threadIdx.x;

    for (int i = tid; i < 64 * 27; i += 256) ws[i] = w1[i];
    if (tid < 64) bs[tid] = b1[tid];

    const float* xin = x + tb * 3 * 1024;
    for (int i = tid; i < 3 * 34 * 34; i += 256) {
        int cin = i / 1156, rem = i - cin * 1156;
        int yy = rem / 34, xx = rem - yy * 34;
        int gy = yy - 1, gx = xx - 1;
        float v = 0.f;
        if (gy >= 0 && gy < 32 && gx >= 0 && gx < 32)
            v = xin[cin * 1024 + gy * 32 + gx];
        xs[cin * 1224 + yy * 36 + xx] = v;
    }
    __syncthreads();

    const int wid  = tid >> 5;
    const int lane = tid & 31;          // channel pair: (lane, lane+32)

    unsigned long long wp[27];
#pragma unroll
    for (int k = 0; k < 27; k++)
        PACKAB(wp[k], ws[lane * 27 + k], ws[(lane + 32) * 27 + k]);
    unsigned long long bias2;
    PACKAB(bias2, bs[lane], bs[lane + 32]);

    for (int seg = wid; seg < 128; seg += 8) {
        const int y   = seg >> 2;
        const int xc0 = (seg & 3) * 8;

        unsigned long long acc2[8];
#pragma unroll
        for (int px = 0; px < 8; px++) acc2[px] = bias2;

#pragma unroll
        for (int cin = 0; cin < 3; cin++) {
            const float* base = xs + cin * 1224 + xc0;
#pragma unroll
            for (int dr = 0; dr < 3; dr++) {
                const float4* rp = (const float4*)(base + (y + dr) * 36);
                float4 f0 = rp[0], f1 = rp[1], f2 = rp[2];
                unsigned long long x2[10];
                PACK2(x2[0], f0.x); PACK2(x2[1], f0.y); PACK2(x2[2], f0.z); PACK2(x2[3], f0.w);
                PACK2(x2[4], f1.x); PACK2(x2[5], f1.y); PACK2(x2[6], f1.z); PACK2(x2[7], f1.w);
                PACK2(x2[8], f2.x); PACK2(x2[9], f2.y);
                const int wb = cin * 9 + dr * 3;
#pragma unroll
                for (int px = 0; px < 8; px++) {
                    FMA2(acc2[px], wp[wb],     x2[px]);
                    FMA2(acc2[px], wp[wb + 1], x2[px + 1]);
                    FMA2(acc2[px], wp[wb + 2], x2[px + 2]);
                }
            }
        }

#pragma unroll
        for (int px = 0; px < 8; px++) {
            float lo, hi;
            UNPACK2(lo, hi, acc2[px]);
            unsigned mlo = __ballot_sync(0xffffffffu, lo >= THR);
            unsigned mhi = __ballot_sync(0xffffffffu, hi >= THR);
            if (lane == 0)
                ((uint2*)g_mask)[tb * 1024 + seg * 8 + px] = make_uint2(mlo, mhi);
        }
    }
}

// ---------------------------------------------------------------------------
// Kernel 2a: split w2 -> bf16 hi+lo, layout [pass][pos][cin][co]
// ---------------------------------------------------------------------------
__global__ void k2a_split(const float* __restrict__ w2) {
    int i = blockIdx.x * 256 + threadIdx.x;
    if (i >= 36864) return;
    int co = i / 576, rest = i - co * 576;
    int cin = rest / 9, pos = rest - cin * 9;
    float w = w2[i];
    __nv_bfloat16 hi = __float2bfloat16(w);
    __nv_bfloat16 lo = __float2bfloat16(w - __bfloat162float(hi));
    int idx = pos * 4096 + cin * 64 + co;
    g_wsp[idx] = hi;
    g_wsp[36864 + idx] = lo;
}

// ---------------------------------------------------------------------------
// Kernel 2b: transpose wfc -> [co*1024+px][12]
// ---------------------------------------------------------------------------
__global__ void k2b_transpose(const float* __restrict__ wfc) {
    int i = blockIdx.x * 256 + threadIdx.x;   // 0..65535
    float v[10];
#pragma unroll
    for (int o = 0; o < 10; o++) v[o] = wfc[o * 65536 + i];
    float4* dst = (float4*)(g_wfcT + i * 12);
    dst[0] = make_float4(v[0], v[1], v[2], v[3]);
    dst[1] = make_float4(v[4], v[5], v[6], v[7]);
    dst[2] = make_float4(v[8], v[9], 0.f, 0.f);
}

// ---------------------------------------------------------------------------
// Kernel 2: conv2 via mma.sync bf16 (hi/lo) + LIF + count over t + FC.
// Grid: (2 strips of 16 rows, 64 b) = 128 CTAs, 512 threads = 16 warps.
// Warp = one image row = TWO m16 tiles (x-halves) sharing all B fragments
// -> B ldmatrix traffic halved vs R10. Spike counts packed 4-per-u32.
// SMEM: thr2 @0 (256B) | red @256 (640B) | LUT @1024 (4KB)
//       weights @5120 (147456B) | plane @152576: 612 rows x 128B (78336B)
//       total 230912
// ---------------------------------------------------------------------------
#define OFF_RED   256
#define OFF_LUT   1024
#define OFF_B     5120
#define OFF_PLANE 152576
#define SMEM_K2   230912

__global__ __launch_bounds__(512, 1) void k2_mma(const float* __restrict__ b2) {
    extern __shared__ __align__(128) char sm[];
    const unsigned smb = smem_u32(sm);

    const int sy  = blockIdx.x;       // 16-row strip (0..1)
    const int b   = blockIdx.y;
    const int tid = threadIdx.x;
    const int wid = tid >> 5;
    const int lane = tid & 31;
    const int ry = wid;               // image row within strip (0..15)

    // LUT: byte -> 8 bf16 (0/1)
    if (tid < 256) {
        int v = tid;
        unsigned w[4];
#pragma unroll
        for (int i = 0; i < 4; i++) {
            unsigned lo = ((v >> (2 * i)) & 1)     ? 0x3F80u : 0u;
            unsigned hi = ((v >> (2 * i + 1)) & 1) ? 0x3F800000u : 0u;
            w[i] = lo | hi;
        }
        *(uint4*)(sm + OFF_LUT + v * 16) = make_uint4(w[0], w[1], w[2], w[3]);
    }
    if (tid < 64) ((float*)sm)[tid] = THR - b2[tid];

    // weights -> SMEM with chunk swizzle j ^= (row&7)
    {
        const char* src = (const char*)g_wsp;
        for (int i = tid; i < 9216; i += 512) {
            int off = i * 16;
            int inner = off & 8191;
            int r = inner >> 7, j = (inner >> 4) & 7;
            uint4 v = *(const uint4*)(src + off);
            *(uint4*)(sm + OFF_B + (off & ~8191) + (r << 7) + ((j ^ (r & 7)) << 4)) = v;
        }
    }
    __syncthreads();

    float thr2v[16];
#pragma unroll
    for (int nf = 0; nf < 8; nf++) {
        thr2v[nf * 2]     = ((const float*)sm)[nf * 8 + (lane & 3) * 2];
        thr2v[nf * 2 + 1] = ((const float*)sm)[nf * 8 + (lane & 3) * 2 + 1];
    }

    // packed spike counters: [tile][nf], 4 q-counts per u32 (bytes)
    unsigned cntp[2][8];
#pragma unroll
    for (int h = 0; h < 2; h++)
#pragma unroll
        for (int nf = 0; nf < 8; nf++) cntp[h][nf] = 0u;

    const uint2* gm = (const uint2*)g_mask;
    const unsigned p0 = smb + OFF_PLANE;

    for (int t = 0; t < 8; t++) {
        // --- expand spike masks for this t: 612 rows (18 image rows + x halo)
        for (int r = tid; r < 612; r += 512) {
            int iy = r / 34, ixp = r - iy * 34;
            int y = sy * 16 - 1 + iy;
            int ix = ixp - 1;
            uint2 m = make_uint2(0u, 0u);
            if ((unsigned)y < 32u && (unsigned)ix < 32u)
                m = gm[(t * 64 + b) * 1024 + y * 32 + ix];
            char* pb = sm + OFF_PLANE + r * 128;
            const int rs = r & 7;
#pragma unroll
            for (int k = 0; k < 4; k++) {
                unsigned byte = (m.x >> (8 * k)) & 0xFFu;
                uint4 v = *(const uint4*)(sm + OFF_LUT + byte * 16);
                *(uint4*)(pb + ((k ^ rs) << 4)) = v;
            }
#pragma unroll
            for (int k = 4; k < 8; k++) {
                unsigned byte = (m.y >> (8 * (k - 4))) & 0xFFu;
                uint4 v = *(const uint4*)(sm + OFF_LUT + byte * 16);
                *(uint4*)(pb + ((k ^ rs) << 4)) = v;
            }
        }
        __syncthreads();

        float c[2][8][4];
#pragma unroll
        for (int h = 0; h < 2; h++)
#pragma unroll
            for (int nf = 0; nf < 8; nf++)
#pragma unroll
                for (int q = 0; q < 4; q++) c[h][nf][q] = 0.f;

#pragma unroll 1
        for (int pos = 0; pos < 9; pos++) {
            const int dy = pos / 3, dx = pos - dy * 3;
            const int prb0 = (ry + dy) * 34 + dx + (lane & 15);        // half 0
            const unsigned wtb = smb + OFF_B + pos * 8192;
#pragma unroll 1
            for (int kt = 0; kt < 4; kt++) {
                const unsigned kcol = (unsigned)(kt * 2 + (lane >> 4));
                const unsigned aoff0 = prb0 * 128 + ((kcol ^ (prb0 & 7)) << 4);
                const int prb1 = prb0 + 16;
                const unsigned aoff1 = prb1 * 128 + ((kcol ^ (prb1 & 7)) << 4);
                unsigned a0[4], a1[4];
                LDMX4(a0, p0 + aoff0);
                LDMX4(a1, p0 + aoff1);
                const int brow = kt * 16 + (lane & 15);
                const unsigned bjb = (unsigned)(lane >> 4);
                const unsigned bbase = brow * 128;
#pragma unroll
                for (int pass = 0; pass < 2; pass++) {
                    const unsigned wb = wtb + pass * 73728 + bbase;
#pragma unroll
                    for (int nt = 0; nt < 4; nt++) {
                        unsigned bb[4];
                        LDMX4T(bb, wb + (((nt * 2 + bjb) ^ (brow & 7)) << 4));
                        MMA16816(c[0][nt * 2],     a0, bb[0], bb[1]);
                        MMA16816(c[0][nt * 2 + 1], a0, bb[2], bb[3]);
                        MMA16816(c[1][nt * 2],     a1, bb[0], bb[1]);
                        MMA16816(c[1][nt * 2 + 1], a1, bb[2], bb[3]);
                    }
                }
            }
        }

        // threshold -> packed spike counts
#pragma unroll
        for (int h = 0; h < 2; h++)
#pragma unroll
            for (int nf = 0; nf < 8; nf++)
#pragma unroll
                for (int q = 0; q < 4; q++)
                    cntp[h][nf] += (c[h][nf][q] >= thr2v[nf * 2 + (q & 1)])
                                       ? (1u << (8 * q)) : 0u;

        __syncthreads();   // MMA reads done before next t overwrites plane
    }

    // --- fused FC fold
    float oa[10];
#pragma unroll
    for (int o = 0; o < 10; o++) oa[o] = 0.f;
#pragma unroll
    for (int h = 0; h < 2; h++) {
        const int gpbase = (sy * 16 + ry) * 32 + h * 16;
#pragma unroll
        for (int q = 0; q < 4; q++) {
            const int gp = gpbase + (lane >> 2) + ((q >> 1) << 3);
#pragma unroll
            for (int nf = 0; nf < 8; nf++) {
                const int co = nf * 8 + (lane & 3) * 2 + (q & 1);
                const float4* p = (const float4*)(g_wfcT + (co * 1024 + gp) * 12);
                float4 f0 = p[0], f1 = p[1], f2 = p[2];
                const float cc = (float)((cntp[h][nf] >> (8 * q)) & 0xFFu);
                oa[0] += cc * f0.x; oa[1] += cc * f0.y; oa[2] += cc * f0.z; oa[3] += cc * f0.w;
                oa[4] += cc * f1.x; oa[5] += cc * f1.y; oa[6] += cc * f1.z; oa[7] += cc * f1.w;
                oa[8] += cc * f2.x; oa[9] += cc * f2.y;
            }
        }
    }

    float* red = (float*)(sm + OFF_RED);
#pragma unroll
    for (int o = 0; o < 10; o++) {
        float v = oa[o];
        v += __shfl_down_sync(0xffffffffu, v, 16);
        v += __shfl_down_sync(0xffffffffu, v, 8);
        v += __shfl_down_sync(0xffffffffu, v, 4);
        v += __shfl_down_sync(0xffffffffu, v, 2);
        v += __shfl_down_sync(0xffffffffu, v, 1);
        if (lane == 0) red[wid * 10 + o] = v;
    }
    __syncthreads();
    if (tid < 10) {
        float s = 0.f;
#pragma unroll
        for (int w = 0; w < 16; w++) s += red[w * 10 + tid];
        g_part[(b * 2 + sy) * 10 + tid] = s;
    }
}

// ---------------------------------------------------------------------------
// Kernel 3: final reduction
// ---------------------------------------------------------------------------
__global__ void k3_final(const float* __restrict__ bfc, float* __restrict__ out) {
    const int tid = threadIdx.x;
    if (tid < 640) {
        const int b = tid / 10, o = tid - b * 10;
        float s = 8.f * bfc[o];
#pragma unroll
        for (int k = 0; k < 2; k++) s += g_part[(b * 2 + k) * 10 + o];
        out[tid] = s;
    }
}

extern "C" void kernel_launch(void* const* d_in, const int* in_sizes, int n_in,
                              void* d_out, int out_size) {
    const float* x   = (const float*)d_in[0];  // [8,64,3,32,32]
    const float* w1  = (const float*)d_in[1];  // [64,3,3,3]
    const float* b1  = (const float*)d_in[2];  // [64]
    const float* w2  = (const float*)d_in[3];  // [64,64,3,3]
    const float* b2  = (const float*)d_in[4];  // [64]
    const float* wfc = (const float*)d_in[5];  // [10, 65536]
    const float* bfc = (const float*)d_in[6];  // [10]
    float* out = (float*)d_out;                // [64,10]

    cudaFuncSetAttribute(k2_mma, cudaFuncAttributeMaxDynamicSharedMemorySize,
                         SMEM_K2);

    k1_conv1<<<512, 256>>>(x, w1, b1);
    k2a_split<<<144, 256>>>(w2);
    k2b_transpose<<<256, 256>>>(wfc);
    k2_mma<<<dim3(2, 64), 512, SMEM_K2>>>(b2);
    k3_final<<<1, 640>>>(bfc, out);
}

// round 12
// speedup vs baseline: 3.4046x; 1.0462x over previous
#include <cuda_runtime.h>
#include <cuda_bf16.h>

#define THR 1.2f

// ---------------------------------------------------------------------------
// Device globals
// ---------------------------------------------------------------------------
__device__ unsigned g_mask[512 * 1024 * 2];          // [t*64+b][px] uint2 channel masks
__device__ float    g_part[256 * 10];                // per-block FC partials
__device__ __nv_bfloat16 g_wsp[2 * 9 * 64 * 64];     // [pass][pos][cin][co] split w2
__device__ float    g_wfcT[65536 * 12];              // [co*1024+px][12] transposed wfc

__device__ __forceinline__ unsigned smem_u32(const void* p) {
    unsigned a;
    asm("{ .reg .u64 t; cvta.to.shared.u64 t, %1; cvt.u32.u64 %0, t; }"
        : "=r"(a) : "l"(p));
    return a;
}

#define LDMX4(r, addr) \
    asm volatile("ldmatrix.sync.aligned.m8n8.x4.shared.b16 {%0,%1,%2,%3}, [%4];" \
        : "=r"((r)[0]), "=r"((r)[1]), "=r"((r)[2]), "=r"((r)[3]) : "r"(addr))
#define LDMX4T(r, addr) \
    asm volatile("ldmatrix.sync.aligned.m8n8.x4.trans.shared.b16 {%0,%1,%2,%3}, [%4];" \
        : "=r"((r)[0]), "=r"((r)[1]), "=r"((r)[2]), "=r"((r)[3]) : "r"(addr))
#define MMA16816(c, a, bb0, bb1) \
    asm volatile("mma.sync.aligned.m16n8k16.row.col.f32.bf16.bf16.f32 " \
        "{%0,%1,%2,%3}, {%4,%5,%6,%7}, {%8,%9}, {%0,%1,%2,%3};" \
        : "+f"((c)[0]), "+f"((c)[1]), "+f"((c)[2]), "+f"((c)[3]) \
        : "r"((a)[0]), "r"((a)[1]), "r"((a)[2]), "r"((a)[3]), "r"(bb0), "r"(bb1))

// packed f32x2 helpers for k1
#define PACK2(d, x)   asm("mov.b64 %0, {%1,%1};" : "=l"(d) : "f"(x))
#define PACKAB(d, a, b) asm("mov.b64 %0, {%1,%2};" : "=l"(d) : "f"(a), "f"(b))
#define FMA2(acc, w, x2) \
    asm("fma.rn.f32x2 %0, %1, %2, %0;" : "+l"(acc) : "l"(w), "l"(x2))
#define UNPACK2(lo, hi, v) \
    asm("mov.b64 {%0,%1}, %2;" : "=f"(lo), "=f"(hi) : "l"(v))

// ---------------------------------------------------------------------------
// Kernel 1: conv1 (3->64) + LIF -> channel bitmasks (unchanged)
// ---------------------------------------------------------------------------
__global__ __launch_bounds__(256) void k1_conv1(const float* __restrict__ x,
                                                const float* __restrict__ w1,
                                                const float* __restrict__ b1) {
    __shared__ float xs[3 * 34 * 36];   // rows padded to 36 for vec4 loads
    __shared__ float ws[64 * 27];
    __shared__ float bs[64];

    const int tb  = blockIdx.x;
    const int tid = threadIdx.x;

    for (int i = tid; i < 64 * 27; i += 256) ws[i] = w1[i];
    if (tid < 64) bs[tid] = b1[tid];

    const float* xin = x + tb * 3 * 1024;
    for (int i = tid; i < 3 * 34 * 34; i += 256) {
        int cin = i / 1156, rem = i - cin * 1156;
        int yy = rem / 34, xx = rem - yy * 34;
        int gy = yy - 1, gx = xx - 1;
        float v = 0.f;
        if (gy >= 0 && gy < 32 && gx >= 0 && gx < 32)
            v = xin[cin * 1024 + gy * 32 + gx];
        xs[cin * 1224 + yy * 36 + xx] = v;
    }
    __syncthreads();

    const int wid  = tid >> 5;
    const int lane = tid & 31;          // channel pair: (lane, lane+32)

    unsigned long long wp[27];
#pragma unroll
    for (int k = 0; k < 27; k++)
        PACKAB(wp[k], ws[lane * 27 + k], ws[(lane + 32) * 27 + k]);
    unsigned long long bias2;
    PACKAB(bias2, bs[lane], bs[lane + 32]);

    for (int seg = wid; seg < 128; seg += 8) {
        const int y   = seg >> 2;
        const int xc0 = (seg & 3) * 8;

        unsigned long long acc2[8];
#pragma unroll
        for (int px = 0; px < 8; px++) acc2[px] = bias2;

#pragma unroll
        for (int cin = 0; cin < 3; cin++) {
            const float* base = xs + cin * 1224 + xc0;
#pragma unroll
            for (int dr = 0; dr < 3; dr++) {
                const float4* rp = (const float4*)(base + (y + dr) * 36);
                float4 f0 = rp[0], f1 = rp[1], f2 = rp[2];
                unsigned long long x2[10];
                PACK2(x2[0], f0.x); PACK2(x2[1], f0.y); PACK2(x2[2], f0.z); PACK2(x2[3], f0.w);
                PACK2(x2[4], f1.x); PACK2(x2[5], f1.y); PACK2(x2[6], f1.z); PACK2(x2[7], f1.w);
                PACK2(x2[8], f2.x); PACK2(x2[9], f2.y);
                const int wb = cin * 9 + dr * 3;
#pragma unroll
                for (int px = 0; px < 8; px++) {
                    FMA2(acc2[px], wp[wb],     x2[px]);
                    FMA2(acc2[px], wp[wb + 1], x2[px + 1]);
                    FMA2(acc2[px], wp[wb + 2], x2[px + 2]);
                }
            }
        }

#pragma unroll
        for (int px = 0; px < 8; px++) {
            float lo, hi;
            UNPACK2(lo, hi, acc2[px]);
            unsigned mlo = __ballot_sync(0xffffffffu, lo >= THR);
            unsigned mhi = __ballot_sync(0xffffffffu, hi >= THR);
            if (lane == 0)
                ((uint2*)g_mask)[tb * 1024 + seg * 8 + px] = make_uint2(mlo, mhi);
        }
    }
}

// ---------------------------------------------------------------------------
// Kernel 2a: split w2 -> bf16 hi+lo, layout [pass][pos][cin][co]
// ---------------------------------------------------------------------------
__global__ void k2a_split(const float* __restrict__ w2) {
    int i = blockIdx.x * 256 + threadIdx.x;
    if (i >= 36864) return;
    int co = i / 576, rest = i - co * 576;
    int cin = rest / 9, pos = rest - cin * 9;
    float w = w2[i];
    __nv_bfloat16 hi = __float2bfloat16(w);
    __nv_bfloat16 lo = __float2bfloat16(w - __bfloat162float(hi));
    int idx = pos * 4096 + cin * 64 + co;
    g_wsp[idx] = hi;
    g_wsp[36864 + idx] = lo;
}

// ---------------------------------------------------------------------------
// Kernel 2b: transpose wfc -> [co*1024+px][12]
// ---------------------------------------------------------------------------
__global__ void k2b_transpose(const float* __restrict__ wfc) {
    int i = blockIdx.x * 256 + threadIdx.x;   // 0..65535
    float v[10];
#pragma unroll
    for (int o = 0; o < 10; o++) v[o] = wfc[o * 65536 + i];
    float4* dst = (float4*)(g_wfcT + i * 12);
    dst[0] = make_float4(v[0], v[1], v[2], v[3]);
    dst[1] = make_float4(v[4], v[5], v[6], v[7]);
    dst[2] = make_float4(v[8], v[9], 0.f, 0.f);
}

// ---------------------------------------------------------------------------
// Kernel 2: conv2 via mma.sync bf16 (hi/lo) + LIF + count over t + FC.
// Grid: (2 strips of 16 rows, 64 b) = 128 CTAs, 256 threads = 8 warps.
// Warp = TWO rows = FOUR m16 tiles sharing all B fragments (4x MMA ILP per
// LDSM, up to 255 regs/thread). Spike counts nibble-packed (8 nf per u32).
// SMEM: thr2 @0 (256B) | red @256 (320B) | LUT @1024 (4KB)
//       weights @5120 (147456B) | plane @152576: 612 rows x 128B (78336B)
// ---------------------------------------------------------------------------
#define OFF_RED   256
#define OFF_LUT   1024
#define OFF_B     5120
#define OFF_PLANE 152576
#define SMEM_K2   230912

__global__ __launch_bounds__(256, 1) void k2_mma(const float* __restrict__ b2) {
    extern __shared__ __align__(128) char sm[];
    const unsigned smb = smem_u32(sm);

    const int sy  = blockIdx.x;       // 16-row strip (0..1)
    const int b   = blockIdx.y;
    const int tid = threadIdx.x;
    const int wid = tid >> 5;
    const int lane = tid & 31;
    const int ry2 = wid * 2;          // first image row of this warp (0..14)

    // LUT: byte -> 8 bf16 (0/1)
    if (tid < 256) {
        int v = tid;
        unsigned w[4];
#pragma unroll
        for (int i = 0; i < 4; i++) {
            unsigned lo = ((v >> (2 * i)) & 1)     ? 0x3F80u : 0u;
            unsigned hi = ((v >> (2 * i + 1)) & 1) ? 0x3F800000u : 0u;
            w[i] = lo | hi;
        }
        *(uint4*)(sm + OFF_LUT + v * 16) = make_uint4(w[0], w[1], w[2], w[3]);
    }
    if (tid < 64) ((float*)sm)[tid] = THR - b2[tid];

    // weights -> SMEM with chunk swizzle j ^= (row&7)
    {
        const char* src = (const char*)g_wsp;
        for (int i = tid; i < 9216; i += 256) {
            int off = i * 16;
            int inner = off & 8191;
            int r = inner >> 7, j = (inner >> 4) & 7;
            uint4 v = *(const uint4*)(src + off);
            *(uint4*)(sm + OFF_B + (off & ~8191) + (r << 7) + ((j ^ (r & 7)) << 4)) = v;
        }
    }
    __syncthreads();

    float thr2v[16];
#pragma unroll
    for (int nf = 0; nf < 8; nf++) {
        thr2v[nf * 2]     = ((const float*)sm)[nf * 8 + (lane & 3) * 2];
        thr2v[nf * 2 + 1] = ((const float*)sm)[nf * 8 + (lane & 3) * 2 + 1];
    }

    // nibble-packed spike counters: cntp[tile][q], nf in nibbles (cnt<=8)
    unsigned cntp[4][4];
#pragma unroll
    for (int h = 0; h < 4; h++)
#pragma unroll
        for (int q = 0; q < 4; q++) cntp[h][q] = 0u;

    const uint2* gm = (const uint2*)g_mask;
    const unsigned p0 = smb + OFF_PLANE;

    for (int t = 0; t < 8; t++) {
        // --- expand spike masks for this t: 612 rows (18 image rows + x halo)
        for (int r = tid; r < 612; r += 256) {
            int iy = r / 34, ixp = r - iy * 34;
            int y = sy * 16 - 1 + iy;
            int ix = ixp - 1;
            uint2 m = make_uint2(0u, 0u);
            if ((unsigned)y < 32u && (unsigned)ix < 32u)
                m = gm[(t * 64 + b) * 1024 + y * 32 + ix];
            char* pb = sm + OFF_PLANE + r * 128;
            const int rs = r & 7;
#pragma unroll
            for (int k = 0; k < 4; k++) {
                unsigned byte = (m.x >> (8 * k)) & 0xFFu;
                uint4 v = *(const uint4*)(sm + OFF_LUT + byte * 16);
                *(uint4*)(pb + ((k ^ rs) << 4)) = v;
            }
#pragma unroll
            for (int k = 4; k < 8; k++) {
                unsigned byte = (m.y >> (8 * (k - 4))) & 0xFFu;
                uint4 v = *(const uint4*)(sm + OFF_LUT + byte * 16);
                *(uint4*)(pb + ((k ^ rs) << 4)) = v;
            }
        }
        __syncthreads();

        float c[4][8][4];   // [tile][nf][q] fp32 accumulators (hi+lo summed)
#pragma unroll
        for (int h = 0; h < 4; h++)
#pragma unroll
            for (int nf = 0; nf < 8; nf++)
#pragma unroll
                for (int q = 0; q < 4; q++) c[h][nf][q] = 0.f;

#pragma unroll 1
        for (int pos = 0; pos < 9; pos++) {
            const int dy = pos / 3, dx = pos - dy * 3;
            const int prbase = (ry2 + dy) * 34 + dx + (lane & 15);
            const unsigned wtb = smb + OFF_B + pos * 8192;
#pragma unroll 1
            for (int kt = 0; kt < 4; kt++) {
                const unsigned kcol = (unsigned)(kt * 2 + (lane >> 4));
                unsigned a[4][4];
#pragma unroll
                for (int h = 0; h < 4; h++) {
                    const int prb = prbase + (h >> 1) * 34 + (h & 1) * 16;
                    LDMX4(a[h], p0 + prb * 128 + ((kcol ^ (prb & 7)) << 4));
                }
                const int brow = kt * 16 + (lane & 15);
                const unsigned bjb = (unsigned)(lane >> 4);
                const unsigned bbase = brow * 128;
#pragma unroll
                for (int pass = 0; pass < 2; pass++) {
                    const unsigned wb = wtb + pass * 73728 + bbase;
#pragma unroll
                    for (int nt = 0; nt < 4; nt++) {
                        unsigned bb[4];
                        LDMX4T(bb, wb + (((nt * 2 + bjb) ^ (brow & 7)) << 4));
#pragma unroll
                        for (int h = 0; h < 4; h++) {
                            MMA16816(c[h][nt * 2],     a[h], bb[0], bb[1]);
                            MMA16816(c[h][nt * 2 + 1], a[h], bb[2], bb[3]);
                        }
                    }
                }
            }
        }

        // threshold -> nibble-packed spike counts
#pragma unroll
        for (int h = 0; h < 4; h++)
#pragma unroll
            for (int nf = 0; nf < 8; nf++)
#pragma unroll
                for (int q = 0; q < 4; q++)
                    cntp[h][q] += (c[h][nf][q] >= thr2v[nf * 2 + (q & 1)])
                                      ? (1u << (4 * nf)) : 0u;

        __syncthreads();   // MMA reads done before next t overwrites plane
    }

    // --- fused FC fold
    float oa[10];
#pragma unroll
    for (int o = 0; o < 10; o++) oa[o] = 0.f;
#pragma unroll
    for (int h = 0; h < 4; h++) {
        const int gpbase = (sy * 16 + ry2 + (h >> 1)) * 32 + (h & 1) * 16;
#pragma unroll
        for (int q = 0; q < 4; q++) {
            const int gp = gpbase + (lane >> 2) + ((q >> 1) << 3);
#pragma unroll
            for (int nf = 0; nf < 8; nf++) {
                const int co = nf * 8 + (lane & 3) * 2 + (q & 1);
                const float4* p = (const float4*)(g_wfcT + (co * 1024 + gp) * 12);
                float4 f0 = p[0], f1 = p[1], f2 = p[2];
                const float cc = (float)((cntp[h][q] >> (4 * nf)) & 0xFu);
                oa[0] += cc * f0.x; oa[1] += cc * f0.y; oa[2] += cc * f0.z; oa[3] += cc * f0.w;
                oa[4] += cc * f1.x; oa[5] += cc * f1.y; oa[6] += cc * f1.z; oa[7] += cc * f1.w;
                oa[8] += cc * f2.x; oa[9] += cc * f2.y;
            }
        }
    }

    float* red = (float*)(sm + OFF_RED);
#pragma unroll
    for (int o = 0; o < 10; o++) {
        float v = oa[o];
        v += __shfl_down_sync(0xffffffffu, v, 16);
        v += __shfl_down_sync(0xffffffffu, v, 8);
        v += __shfl_down_sync(0xffffffffu, v, 4);
        v += __shfl_down_sync(0xffffffffu, v, 2);
        v += __shfl_down_sync(0xffffffffu, v, 1);
        if (lane == 0) red[wid * 10 + o] = v;
    }
    __syncthreads();
    if (tid < 10) {
        float s = 0.f;
#pragma unroll
        for (int w = 0; w < 8; w++) s += red[w * 10 + tid];
        g_part[(b * 2 + sy) * 10 + tid] = s;
    }
}

// ---------------------------------------------------------------------------
// Kernel 3: final reduction
// ---------------------------------------------------------------------------
__global__ void k3_final(const float* __restrict__ bfc, float* __restrict__ out) {
    const int tid = threadIdx.x;
    if (tid < 640) {
        const int b = tid / 10, o = tid - b * 10;
        float s = 8.f * bfc[o];
#pragma unroll
        for (int k = 0; k < 2; k++) s += g_part[(b * 2 + k) * 10 + o];
        out[tid] = s;
    }
}

extern "C" void kernel_launch(void* const* d_in, const int* in_sizes, int n_in,
                              void* d_out, int out_size) {
    const float* x   = (const float*)d_in[0];  // [8,64,3,32,32]
    const float* w1  = (const float*)d_in[1];  // [64,3,3,3]
    const float* b1  = (const float*)d_in[2];  // [64]
    const float* w2  = (const float*)d_in[3];  // [64,64,3,3]
    const float* b2  = (const float*)d_in[4];  // [64]
    const float* wfc = (const float*)d_in[5];  // [10, 65536]
    const float* bfc = (const float*)d_in[6];  // [10]
    float* out = (float*)d_out;                // [64,10]

    cudaFuncSetAttribute(k2_mma, cudaFuncAttributeMaxDynamicSharedMemorySize,
                         SMEM_K2);

    k1_conv1<<<512, 256>>>(x, w1, b1);
    k2a_split<<<144, 256>>>(w2);
    k2b_transpose<<<256, 256>>>(wfc);
    k2_mma<<<dim3(2, 64), 256, SMEM_K2>>>(b2);
    k3_final<<<1, 640>>>(bfc, out);
}